// round 5
// baseline (speedup 1.0000x reference)
#include <cuda_runtime.h>
#include <cuda_bf16.h>
#include <cstdint>

// Problem constants
#define Bv   32
#define Nv   128
#define Fv   78
#define Hv   256
#define Sv   20
#define Tv   13
#define Lv   3
#define ALPHA 0.2f
#define NEG_INF -9000000000000000.0f

#define BN (Bv*Nv)          // 4096 rows

// Scratch (device globals; no allocation allowed)
__device__ float g_xT[Hv*BN];                 // activations TRANSPOSED [c][row]
__device__ float g_h[BN*Hv];                  // projected h, normal [row][c]
__device__ float g_zbuf[Lv*2*BN + Bv*Hv];     // s1/s2 per layer + graph accum

#define GRAPH_OFF (Lv*2*BN)

// ---------------------------------------------------------------------------
// packed fp32x2 helpers (sm_100+: fma.rn.f32x2)
// ---------------------------------------------------------------------------
typedef unsigned long long u64;

__device__ __forceinline__ void fma2(u64& d, u64 a, u64 b) {
    asm("fma.rn.f32x2 %0, %1, %2, %0;" : "+l"(d) : "l"(a), "l"(b));
}
__device__ __forceinline__ u64 pack2(float lo, float hi) {
    u64 r;
    asm("mov.b64 %0, {%1, %2};" : "=l"(r) : "f"(lo), "f"(hi));
    return r;
}
__device__ __forceinline__ float2 unpack2(u64 p) {
    float lo, hi;
    asm("mov.b64 {%0, %1}, %2;" : "=f"(lo), "=f"(hi) : "l"(p));
    return make_float2(lo, hi);
}

// cp.async helpers
__device__ __forceinline__ void cp16(uint32_t s, const void* g) {
    asm volatile("cp.async.ca.shared.global [%0], [%1], 16;" :: "r"(s), "l"(g));
}
#define CP_COMMIT() asm volatile("cp.async.commit_group;")
#define CP_WAIT1()  asm volatile("cp.async.wait_group 1;")
#define CP_WAIT0()  asm volatile("cp.async.wait_group 0;")

// ---------------------------------------------------------------------------
// K1: x = node_features @ W_node + b_node -> g_xT (transposed)
// ---------------------------------------------------------------------------
#define NP_ROWS 8
__global__ void k_node_proj(const float* __restrict__ nf,
                            const float* __restrict__ W,
                            const float* __restrict__ bias)
{
    int row0 = blockIdx.x * NP_ROWS;
    int j    = threadIdx.x;

    __shared__ __align__(16) float sf[Fv * NP_ROWS];   // [f][r]
    __shared__ float st[NP_ROWS * 257];                // transpose tile

    for (int idx = j; idx < Fv*NP_ROWS; idx += 256) {
        int f = idx >> 3, r = idx & 7;
        sf[idx] = nf[(row0 + r)*Fv + f];
    }
    __syncthreads();

    float bj = bias[j];
    float acc[NP_ROWS];
#pragma unroll
    for (int r = 0; r < NP_ROWS; ++r) acc[r] = bj;

#pragma unroll 6
    for (int f = 0; f < Fv; ++f) {
        float w = W[f*Hv + j];
        const float4* xp = reinterpret_cast<const float4*>(&sf[f*NP_ROWS]);
        float4 xa = xp[0], xb = xp[1];
        acc[0] += xa.x * w;  acc[1] += xa.y * w;
        acc[2] += xa.z * w;  acc[3] += xa.w * w;
        acc[4] += xb.x * w;  acc[5] += xb.y * w;
        acc[6] += xb.z * w;  acc[7] += xb.w * w;
    }

#pragma unroll
    for (int r = 0; r < NP_ROWS; ++r)
        st[r*257 + j] = acc[r];
    __syncthreads();
    int r  = j & 7;
    int cb = j >> 3;          // 0..31
#pragma unroll
    for (int p = 0; p < 8; ++p) {
        int c = cb + 32*p;
        g_xT[(size_t)c*BN + row0 + r] = st[r*257 + c];
    }
}

// ---------------------------------------------------------------------------
// K2: h = x @ gat_W[l] + partial scores.
// 64 threads, tile 64 rows x 64 cols, thread = 8x8 via split tiles,
// packed f32x2 FMAs, cp.async double-buffered staging.
// ---------------------------------------------------------------------------
#define KCp 32
__global__ void k_gat_proj(const float* __restrict__ W,   // [256,256]
                           const float* __restrict__ a,   // [512]
                           int layer)
{
    const int row0 = blockIdx.x * 64;
    const int c0   = blockIdx.y * 64;
    const int t  = threadIdx.x;           // 0..63
    const int tx = t & 7, ty = t >> 3;    // 8 x 8

    float* s1 = g_zbuf + layer*2*BN;
    float* s2 = s1 + BN;

    __shared__ __align__(16) float sx[2][KCp*64];   // [k][row]
    __shared__ __align__(16) float sw[2][KCp*64];   // [k][col]

    const uint32_t sxa = (uint32_t)__cvta_generic_to_shared(sx);
    const uint32_t swa = (uint32_t)__cvta_generic_to_shared(sw);

    // staging mapping: k = kq + 8m (m<4), two 16B pieces at fq*16 and fq*16+128
    const int kq = t >> 3, fq = t & 7;
    const float* xT = g_xT;

#define ISSUE_CHUNK(kc, buf)                                                   \
    {                                                                          \
        _Pragma("unroll")                                                      \
        for (int m = 0; m < 4; ++m) {                                          \
            int k = kq + 8*m;                                                  \
            uint32_t sxd = sxa + ((buf)*KCp*64 + k*64)*4 + fq*16;              \
            const float* xg = &xT[(size_t)((kc)+k)*BN + row0 + fq*4];          \
            cp16(sxd,       xg);                                               \
            cp16(sxd + 128, xg + 32);                                          \
            uint32_t swd = swa + ((buf)*KCp*64 + k*64)*4 + fq*16;              \
            const float* wg = &W[((kc)+k)*Hv + c0 + fq*4];                     \
            cp16(swd,       wg);                                               \
            cp16(swd + 128, wg + 32);                                          \
        }                                                                      \
        CP_COMMIT();                                                           \
    }

    u64 acc[8][4];
#pragma unroll
    for (int r = 0; r < 8; ++r)
#pragma unroll
        for (int p = 0; p < 4; ++p) acc[r][p] = pack2(0.f, 0.f);

    ISSUE_CHUNK(0, 0);

    const int NCH = Hv / KCp;      // 8
#pragma unroll
    for (int c = 0; c < NCH; ++c) {
        const int cur = c & 1;
        if (c + 1 < NCH) {
            ISSUE_CHUNK((c+1)*KCp, (c+1)&1);
            CP_WAIT1();
        } else {
            CP_WAIT0();
        }
        __syncthreads();

#pragma unroll 8
        for (int k = 0; k < KCp; ++k) {
            float4 xa = *reinterpret_cast<const float4*>(&sx[cur][k*64 + ty*4]);
            float4 xb = *reinterpret_cast<const float4*>(&sx[cur][k*64 + 32 + ty*4]);
            float4 wa = *reinterpret_cast<const float4*>(&sw[cur][k*64 + tx*4]);
            float4 wb = *reinterpret_cast<const float4*>(&sw[cur][k*64 + 32 + tx*4]);
            u64 wp0 = pack2(wa.x, wa.y), wp1 = pack2(wa.z, wa.w);
            u64 wp2 = pack2(wb.x, wb.y), wp3 = pack2(wb.z, wb.w);
            u64 xd[8];
            xd[0] = pack2(xa.x, xa.x); xd[1] = pack2(xa.y, xa.y);
            xd[2] = pack2(xa.z, xa.z); xd[3] = pack2(xa.w, xa.w);
            xd[4] = pack2(xb.x, xb.x); xd[5] = pack2(xb.y, xb.y);
            xd[6] = pack2(xb.z, xb.z); xd[7] = pack2(xb.w, xb.w);
#pragma unroll
            for (int r = 0; r < 8; ++r) {
                fma2(acc[r][0], xd[r], wp0);
                fma2(acc[r][1], xd[r], wp1);
                fma2(acc[r][2], xd[r], wp2);
                fma2(acc[r][3], xd[r], wp3);
            }
        }
        __syncthreads();
    }
#undef ISSUE_CHUNK

    // epilogue: unpack, store h, reduce scores
    float4 a1a = *reinterpret_cast<const float4*>(&a[c0 + tx*4]);
    float4 a1b = *reinterpret_cast<const float4*>(&a[c0 + 32 + tx*4]);
    float4 a2a = *reinterpret_cast<const float4*>(&a[Hv + c0 + tx*4]);
    float4 a2b = *reinterpret_cast<const float4*>(&a[Hv + c0 + 32 + tx*4]);

#pragma unroll
    for (int r = 0; r < 8; ++r) {
        int row = row0 + ((r < 4) ? (ty*4 + r) : (32 + ty*4 + r - 4));
        float2 v0 = unpack2(acc[r][0]);
        float2 v1 = unpack2(acc[r][1]);
        float2 v2 = unpack2(acc[r][2]);
        float2 v3 = unpack2(acc[r][3]);
        *reinterpret_cast<float4*>(&g_h[(size_t)row*Hv + c0 + tx*4]) =
            make_float4(v0.x, v0.y, v1.x, v1.y);
        *reinterpret_cast<float4*>(&g_h[(size_t)row*Hv + c0 + 32 + tx*4]) =
            make_float4(v2.x, v2.y, v3.x, v3.y);

        float p1 = v0.x*a1a.x + v0.y*a1a.y + v1.x*a1a.z + v1.y*a1a.w
                 + v2.x*a1b.x + v2.y*a1b.y + v3.x*a1b.z + v3.y*a1b.w;
        float p2 = v0.x*a2a.x + v0.y*a2a.y + v1.x*a2a.z + v1.y*a2a.w
                 + v2.x*a2b.x + v2.y*a2b.y + v3.x*a2b.z + v3.y*a2b.w;
#pragma unroll
        for (int off = 4; off > 0; off >>= 1) {       // reduce across tx (8 lanes)
            p1 += __shfl_xor_sync(0xffffffffu, p1, off);
            p2 += __shfl_xor_sync(0xffffffffu, p2, off);
        }
        if (tx == 0) {
            atomicAdd(&s1[row], p1);
            atomicAdd(&s2[row], p2);
        }
    }
}

// ---------------------------------------------------------------------------
// K3: softmax attention + aggregation (+ fused mean on last layer)
// 64 threads, tile 64 att-rows x 64 channels, 8x8/thread, f32x2.
// ---------------------------------------------------------------------------
#define JCc 16
#define ATS 68
__global__ void k_gat_agg(const int* __restrict__ adj, int layer, int last)
{
    const int b  = blockIdx.z;
    const int i0 = blockIdx.x * 64;
    const int c0 = blockIdx.y * 64;
    const int t  = threadIdx.x;            // 0..63
    const int tx = t & 7, ty = t >> 3;
    const int lane = t & 31, warp = t >> 5;

    const float* s1 = g_zbuf + layer*2*BN;
    const float* s2 = s1 + BN;

    __shared__ float s2_sh[Nv];
    __shared__ __align__(16) float att[Nv * ATS];     // [j][i_local]
    __shared__ __align__(16) float sh[2][JCc * 64];   // h chunks [j][c]

    const uint32_t sha = (uint32_t)__cvta_generic_to_shared(sh);
    const float* hb = g_h + (size_t)b*Nv*Hv;
    const int kq = t >> 3, fq = t & 7;

#define ISSUE_H(jc, buf)                                                       \
    {                                                                          \
        _Pragma("unroll")                                                      \
        for (int m = 0; m < 2; ++m) {                                          \
            int k = kq + 8*m;                                                  \
            uint32_t sd = sha + ((buf)*JCc*64 + k*64)*4 + fq*16;               \
            const float* hg = &hb[(size_t)((jc)+k)*Hv + c0 + fq*4];            \
            cp16(sd,       hg);                                                \
            cp16(sd + 128, hg + 32);                                           \
        }                                                                      \
        CP_COMMIT();                                                           \
    }

    ISSUE_H(0, 0);       // overlap with softmax

    if (t < Nv) s2_sh[t] = s2[b*Nv + t];
    if (t + 64 < Nv) s2_sh[t + 64] = s2[b*Nv + t + 64];
    __syncthreads();

    // softmax: 32 rows per warp
#pragma unroll 4
    for (int rr = 0; rr < 32; ++rr) {
        int il = warp*32 + rr;
        int i  = i0 + il;
        float s1i = s1[b*Nv + i];
        const int* adj_row = adj + (size_t)(b*Nv + i)*Nv;
        float e[4];
        float mx = NEG_INF;
#pragma unroll
        for (int q = 0; q < 4; ++q) {
            int jj = lane + q*32;
            float v = s1i + s2_sh[jj];
            v = (v > 0.f) ? v : ALPHA * v;
            v = (adj_row[jj] > 0) ? v : NEG_INF;
            e[q] = v;
            mx = fmaxf(mx, v);
        }
#pragma unroll
        for (int off = 16; off > 0; off >>= 1)
            mx = fmaxf(mx, __shfl_xor_sync(0xffffffffu, mx, off));
        float sum = 0.f;
#pragma unroll
        for (int q = 0; q < 4; ++q) { e[q] = __expf(e[q] - mx); sum += e[q]; }
#pragma unroll
        for (int off = 16; off > 0; off >>= 1)
            sum += __shfl_xor_sync(0xffffffffu, sum, off);
        float inv = 1.f / sum;
#pragma unroll
        for (int q = 0; q < 4; ++q)
            att[(lane + q*32)*ATS + il] = e[q] * inv;
    }

    u64 acc[4][8];
#pragma unroll
    for (int p = 0; p < 4; ++p)
#pragma unroll
        for (int c = 0; c < 8; ++c) acc[p][c] = pack2(0.f, 0.f);

    const int NJC = Nv / JCc;      // 8
#pragma unroll
    for (int c = 0; c < NJC; ++c) {
        const int cur = c & 1;
        if (c + 1 < NJC) {
            ISSUE_H((c+1)*JCc, (c+1)&1);
            CP_WAIT1();
        } else {
            CP_WAIT0();
        }
        __syncthreads();

#pragma unroll 8
        for (int k = 0; k < JCc; ++k) {
            int j = c*JCc + k;
            float4 ia = *reinterpret_cast<const float4*>(&att[j*ATS + ty*4]);
            float4 ib = *reinterpret_cast<const float4*>(&att[j*ATS + 32 + ty*4]);
            float4 ha = *reinterpret_cast<const float4*>(&sh[cur][k*64 + tx*4]);
            float4 hz = *reinterpret_cast<const float4*>(&sh[cur][k*64 + 32 + tx*4]);
            u64 ip0 = pack2(ia.x, ia.y), ip1 = pack2(ia.z, ia.w);
            u64 ip2 = pack2(ib.x, ib.y), ip3 = pack2(ib.z, ib.w);
            u64 hd[8];
            hd[0] = pack2(ha.x, ha.x); hd[1] = pack2(ha.y, ha.y);
            hd[2] = pack2(ha.z, ha.z); hd[3] = pack2(ha.w, ha.w);
            hd[4] = pack2(hz.x, hz.x); hd[5] = pack2(hz.y, hz.y);
            hd[6] = pack2(hz.z, hz.z); hd[7] = pack2(hz.w, hz.w);
#pragma unroll
            for (int cc = 0; cc < 8; ++cc) {
                fma2(acc[0][cc], ip0, hd[cc]);
                fma2(acc[1][cc], ip1, hd[cc]);
                fma2(acc[2][cc], ip2, hd[cc]);
                fma2(acc[3][cc], ip3, hd[cc]);
            }
        }
        __syncthreads();
    }
#undef ISSUE_H

    // epilogue: out[i][c], i pairs: ip0:(ty*4+0,1) ip1:(+2,+3) ip2:(32+ty*4+0,1) ip3:(+2,+3)
    if (last) {
        float* graph = g_zbuf + GRAPH_OFF;
#pragma unroll
        for (int cc = 0; cc < 8; ++cc) {
            int ccol = (cc < 4) ? (tx*4 + cc) : (32 + tx*4 + cc - 4);
            float p = 0.f;
#pragma unroll
            for (int ip = 0; ip < 4; ++ip) {
                float2 v = unpack2(acc[ip][cc]);
                p += fmaxf(v.x, 0.f) + fmaxf(v.y, 0.f);
            }
            atomicAdd(&graph[b*Hv + c0 + ccol], p);
        }
    } else {
        // transpose relu through smem (reuse att: st[i][c], stride 65)
        __syncthreads();
        float* st = att;
#pragma unroll
        for (int ip = 0; ip < 4; ++ip) {
            int ibase = (ip < 2) ? (ty*4 + 2*ip) : (32 + ty*4 + 2*(ip-2));
#pragma unroll
            for (int cc = 0; cc < 8; ++cc) {
                int ccol = (cc < 4) ? (tx*4 + cc) : (32 + tx*4 + cc - 4);
                float2 v = unpack2(acc[ip][cc]);
                st[ibase*65 + ccol]     = fmaxf(v.x, 0.f);
                st[(ibase+1)*65 + ccol] = fmaxf(v.y, 0.f);
            }
        }
        __syncthreads();
        // thread t owns channel c0+t: write 64 rows as 16 float4
        float* dst = &g_xT[(size_t)(c0 + t)*BN + b*Nv + i0];
#pragma unroll
        for (int q = 0; q < 16; ++q) {
            float4 o = make_float4(st[(4*q+0)*65 + t], st[(4*q+1)*65 + t],
                                   st[(4*q+2)*65 + t], st[(4*q+3)*65 + t]);
            *reinterpret_cast<float4*>(dst + 4*q) = o;
        }
    }
}

// ---------------------------------------------------------------------------
// K5: fused head. One block per batch element.
// ---------------------------------------------------------------------------
__global__ void k_head(const float* __restrict__ scaffold,
                       const float* __restrict__ W_sc,
                       const float* __restrict__ b_sc,
                       const float* __restrict__ gp_w1,
                       const float* __restrict__ gp_b1,
                       const float* __restrict__ gp_w2,
                       const float* __restrict__ gp_b2,
                       const float* __restrict__ out_w1,
                       const float* __restrict__ out_b1,
                       const float* __restrict__ out_w2,
                       const float* __restrict__ out_b2,
                       float* __restrict__ out)
{
    int b = blockIdx.x, t = threadIdx.x;
    const float* graph = g_zbuf + GRAPH_OFF;
    __shared__ float scaf[Sv];
    __shared__ float grow[Hv];
    __shared__ float sc[Hv];
    __shared__ float g1[128], sp1[128];
    __shared__ float c[128];
    __shared__ float hdn[128];

    if (t < Sv) scaf[t] = scaffold[b*Sv + t];
    grow[t] = graph[b*Hv + t] * (1.0f/Nv);
    __syncthreads();

    {
        float acc = b_sc[t];
#pragma unroll
        for (int k = 0; k < Sv; ++k)
            acc += scaf[k] * W_sc[k*Hv + t];
        sc[t] = acc;
    }
    __syncthreads();

    {
        int col = t & 127;
        const float* src = (t < 128) ? grow : sc;
        float acc = gp_b1[col];
#pragma unroll 4
        for (int k = 0; k < Hv; ++k)
            acc += src[k] * gp_w1[k*128 + col];
        acc = fmaxf(acc, 0.f);
        if (t < 128) g1[col] = acc; else sp1[col] = acc;
    }
    __syncthreads();

    if (t < 128) {
        int col = t & 63;
        const float* src = (t < 64) ? g1 : sp1;
        float acc = gp_b2[col];
#pragma unroll 4
        for (int k = 0; k < 128; ++k)
            acc += src[k] * gp_w2[k*64 + col];
        c[t] = fmaxf(acc, 0.f);
    }
    __syncthreads();

    if (t < 128) {
        float acc = out_b1[t];
#pragma unroll 4
        for (int k = 0; k < 128; ++k)
            acc += c[k] * out_w1[k*128 + t];
        hdn[t] = fmaxf(acc, 0.f);
    }
    __syncthreads();

    if (t < Tv) {
        float acc = out_b2[t];
#pragma unroll 4
        for (int k = 0; k < 128; ++k)
            acc += hdn[k] * out_w2[k*Tv + t];
        out[b*Tv + t] = acc;
    }
}

// ---------------------------------------------------------------------------
extern "C" void kernel_launch(void* const* d_in, const int* in_sizes, int n_in,
                              void* d_out, int out_size)
{
    const float* node_features     = (const float*)d_in[0];
    // d_in[1] = edge_features — unused by the reference
    const int*   adj_matrix        = (const int*)  d_in[2];
    const float* scaffold_features = (const float*)d_in[3];
    const float* W_node            = (const float*)d_in[4];
    const float* b_node            = (const float*)d_in[5];
    const float* gat_W             = (const float*)d_in[6];
    const float* gat_a             = (const float*)d_in[7];
    const float* W_sc              = (const float*)d_in[8];
    const float* b_sc              = (const float*)d_in[9];
    const float* gp_w1             = (const float*)d_in[10];
    const float* gp_b1             = (const float*)d_in[11];
    const float* gp_w2             = (const float*)d_in[12];
    const float* gp_b2             = (const float*)d_in[13];
    const float* out_w1            = (const float*)d_in[14];
    const float* out_b1            = (const float*)d_in[15];
    const float* out_w2            = (const float*)d_in[16];
    const float* out_b2            = (const float*)d_in[17];
    float* out = (float*)d_out;

    void* zp = nullptr;
    cudaGetSymbolAddress(&zp, g_zbuf);
    cudaMemsetAsync(zp, 0, (Lv*2*BN + Bv*Hv)*sizeof(float));

    k_node_proj<<<BN/NP_ROWS, 256>>>(node_features, W_node, b_node);

    for (int l = 0; l < Lv; ++l) {
        dim3 pg(BN/64, Hv/64);                 // 64 x 4 = 256 blocks, 64 thr
        k_gat_proj<<<pg, 64>>>(gat_W + (size_t)l*Hv*Hv,
                               gat_a + (size_t)l*2*Hv, l);
        dim3 ag(Nv/64, Hv/64, Bv);             // 2 x 4 x 32 = 256 blocks, 64 thr
        k_gat_agg<<<ag, 64>>>(adj_matrix, l, l == Lv-1);
    }

    k_head<<<Bv, 256>>>(scaffold_features, W_sc, b_sc,
                        gp_w1, gp_b1, gp_w2, gp_b2,
                        out_w1, out_b1, out_w2, out_b2, out);
}

// round 6
// speedup vs baseline: 1.2082x; 1.2082x over previous
#include <cuda_runtime.h>
#include <cuda_bf16.h>
#include <cstdint>

// Problem constants
#define Bv   32
#define Nv   128
#define Fv   78
#define Hv   256
#define Sv   20
#define Tv   13
#define Lv   3
#define ALPHA 0.2f
#define NEG_INF -9000000000000000.0f

#define BN (Bv*Nv)          // 4096 rows

// Scratch (device globals; no allocation allowed)
__device__ float g_xT[Hv*BN];                 // activations TRANSPOSED [c][row]
__device__ float g_h[BN*Hv];                  // projected h, normal [row][c]
__device__ float g_zbuf[Lv*2*BN + Bv*Hv];     // s1/s2 per layer + graph accum

#define GRAPH_OFF (Lv*2*BN)

// ---------------------------------------------------------------------------
// packed fp32x2 helpers
// ---------------------------------------------------------------------------
typedef unsigned long long u64;

__device__ __forceinline__ void fma2(u64& d, u64 a, u64 b) {
    asm("fma.rn.f32x2 %0, %1, %2, %0;" : "+l"(d) : "l"(a), "l"(b));
}
__device__ __forceinline__ u64 pack2(float lo, float hi) {
    u64 r;
    asm("mov.b64 %0, {%1, %2};" : "=l"(r) : "f"(lo), "f"(hi));
    return r;
}
__device__ __forceinline__ float2 unpack2(u64 p) {
    float lo, hi;
    asm("mov.b64 {%0, %1}, %2;" : "=f"(lo), "=f"(hi) : "l"(p));
    return make_float2(lo, hi);
}

// cp.async helpers
__device__ __forceinline__ void cp16(uint32_t s, const void* g) {
    asm volatile("cp.async.ca.shared.global [%0], [%1], 16;" :: "r"(s), "l"(g));
}
#define CP_COMMIT() asm volatile("cp.async.commit_group;")
#define CP_WAIT1()  asm volatile("cp.async.wait_group 1;")
#define CP_WAIT0()  asm volatile("cp.async.wait_group 0;")

// ---------------------------------------------------------------------------
// K1: x = node_features @ W_node + b_node -> g_xT (transposed)
// ---------------------------------------------------------------------------
#define NP_ROWS 8
__global__ void k_node_proj(const float* __restrict__ nf,
                            const float* __restrict__ W,
                            const float* __restrict__ bias)
{
    int row0 = blockIdx.x * NP_ROWS;
    int j    = threadIdx.x;

    __shared__ __align__(16) float sf[Fv * NP_ROWS];   // [f][r]
    __shared__ float st[NP_ROWS * 257];                // transpose tile

    for (int idx = j; idx < Fv*NP_ROWS; idx += 256) {
        int f = idx >> 3, r = idx & 7;
        sf[idx] = nf[(row0 + r)*Fv + f];
    }
    __syncthreads();

    float bj = bias[j];
    float acc[NP_ROWS];
#pragma unroll
    for (int r = 0; r < NP_ROWS; ++r) acc[r] = bj;

#pragma unroll 6
    for (int f = 0; f < Fv; ++f) {
        float w = W[f*Hv + j];
        const float4* xp = reinterpret_cast<const float4*>(&sf[f*NP_ROWS]);
        float4 xa = xp[0], xb = xp[1];
        acc[0] += xa.x * w;  acc[1] += xa.y * w;
        acc[2] += xa.z * w;  acc[3] += xa.w * w;
        acc[4] += xb.x * w;  acc[5] += xb.y * w;
        acc[6] += xb.z * w;  acc[7] += xb.w * w;
    }

#pragma unroll
    for (int r = 0; r < NP_ROWS; ++r)
        st[r*257 + j] = acc[r];
    __syncthreads();
    int r  = j & 7;
    int cb = j >> 3;          // 0..31
#pragma unroll
    for (int p = 0; p < 8; ++p) {
        int c = cb + 32*p;
        g_xT[(size_t)c*BN + row0 + r] = st[r*257 + c];
    }
}

// ---------------------------------------------------------------------------
// K2: h = x @ gat_W[l] + partial scores.
// 128 threads, tile 64 rows x 64 cols, thread = 4 rows x 8 cols, f32x2.
// ---------------------------------------------------------------------------
#define KCp 32
__global__ void k_gat_proj(const float* __restrict__ W,   // [256,256]
                           const float* __restrict__ a,   // [512]
                           int layer)
{
    const int row0 = blockIdx.x * 64;
    const int c0   = blockIdx.y * 64;
    const int t  = threadIdx.x;           // 0..127
    const int tx = t & 7, ty = t >> 3;    // tx 0..7 (cols), ty 0..15 (rows)

    float* s1 = g_zbuf + layer*2*BN;
    float* s2 = s1 + BN;

    __shared__ __align__(16) float sx[2][KCp*64];   // [k][row]
    __shared__ __align__(16) float sw[2][KCp*64];   // [k][col]

    const uint32_t sxa = (uint32_t)__cvta_generic_to_shared(sx);
    const uint32_t swa = (uint32_t)__cvta_generic_to_shared(sw);
    const float* xT = g_xT;

    // staging: 512 x 16B per array per chunk, 128 threads -> 4 each
#define ISSUE_CHUNK(kc, buf)                                                   \
    {                                                                          \
        _Pragma("unroll")                                                      \
        for (int m = 0; m < 4; ++m) {                                          \
            int idx = t + 128*m;                                               \
            int k = idx >> 4, f = idx & 15;                                    \
            uint32_t off = ((buf)*KCp*64 + k*64 + f*4)*4;                      \
            cp16(sxa + off, &xT[(size_t)((kc)+k)*BN + row0 + f*4]);            \
            cp16(swa + off, &W[((kc)+k)*Hv + c0 + f*4]);                       \
        }                                                                      \
        CP_COMMIT();                                                           \
    }

    u64 acc[4][4];
#pragma unroll
    for (int r = 0; r < 4; ++r)
#pragma unroll
        for (int p = 0; p < 4; ++p) acc[r][p] = pack2(0.f, 0.f);

    ISSUE_CHUNK(0, 0);

    const int NCH = Hv / KCp;      // 8
#pragma unroll
    for (int c = 0; c < NCH; ++c) {
        const int cur = c & 1;
        if (c + 1 < NCH) {
            ISSUE_CHUNK((c+1)*KCp, (c+1)&1);
            CP_WAIT1();
        } else {
            CP_WAIT0();
        }
        __syncthreads();

#pragma unroll 8
        for (int k = 0; k < KCp; ++k) {
            float4 xa = *reinterpret_cast<const float4*>(&sx[cur][k*64 + ty*4]);
            const u64* wp = reinterpret_cast<const u64*>(&sw[cur][k*64 + tx*4]);
            const u64* wq = reinterpret_cast<const u64*>(&sw[cur][k*64 + 32 + tx*4]);
            u64 w0 = wp[0], w1 = wp[1], w2 = wq[0], w3 = wq[1];
            u64 x0 = pack2(xa.x, xa.x);
            u64 x1 = pack2(xa.y, xa.y);
            u64 x2 = pack2(xa.z, xa.z);
            u64 x3 = pack2(xa.w, xa.w);
            fma2(acc[0][0], x0, w0); fma2(acc[0][1], x0, w1);
            fma2(acc[0][2], x0, w2); fma2(acc[0][3], x0, w3);
            fma2(acc[1][0], x1, w0); fma2(acc[1][1], x1, w1);
            fma2(acc[1][2], x1, w2); fma2(acc[1][3], x1, w3);
            fma2(acc[2][0], x2, w0); fma2(acc[2][1], x2, w1);
            fma2(acc[2][2], x2, w2); fma2(acc[2][3], x2, w3);
            fma2(acc[3][0], x3, w0); fma2(acc[3][1], x3, w1);
            fma2(acc[3][2], x3, w2); fma2(acc[3][3], x3, w3);
        }
        __syncthreads();
    }
#undef ISSUE_CHUNK

    // epilogue: unpack, store h, reduce scores across the 8 tx lanes
    float4 a1a = *reinterpret_cast<const float4*>(&a[c0 + tx*4]);
    float4 a1b = *reinterpret_cast<const float4*>(&a[c0 + 32 + tx*4]);
    float4 a2a = *reinterpret_cast<const float4*>(&a[Hv + c0 + tx*4]);
    float4 a2b = *reinterpret_cast<const float4*>(&a[Hv + c0 + 32 + tx*4]);

#pragma unroll
    for (int r = 0; r < 4; ++r) {
        int row = row0 + ty*4 + r;
        float2 v0 = unpack2(acc[r][0]);
        float2 v1 = unpack2(acc[r][1]);
        float2 v2 = unpack2(acc[r][2]);
        float2 v3 = unpack2(acc[r][3]);
        *reinterpret_cast<float4*>(&g_h[(size_t)row*Hv + c0 + tx*4]) =
            make_float4(v0.x, v0.y, v1.x, v1.y);
        *reinterpret_cast<float4*>(&g_h[(size_t)row*Hv + c0 + 32 + tx*4]) =
            make_float4(v2.x, v2.y, v3.x, v3.y);

        float p1 = v0.x*a1a.x + v0.y*a1a.y + v1.x*a1a.z + v1.y*a1a.w
                 + v2.x*a1b.x + v2.y*a1b.y + v3.x*a1b.z + v3.y*a1b.w;
        float p2 = v0.x*a2a.x + v0.y*a2a.y + v1.x*a2a.z + v1.y*a2a.w
                 + v2.x*a2b.x + v2.y*a2b.y + v3.x*a2b.z + v3.y*a2b.w;
#pragma unroll
        for (int off = 4; off > 0; off >>= 1) {
            p1 += __shfl_xor_sync(0xffffffffu, p1, off);
            p2 += __shfl_xor_sync(0xffffffffu, p2, off);
        }
        if (tx == 0) {
            atomicAdd(&s1[row], p1);
            atomicAdd(&s2[row], p2);
        }
    }
}

// ---------------------------------------------------------------------------
// K3: softmax attention + aggregation (+ fused mean on last layer)
// 128 threads, tile 64 att-rows x 64 channels, 4x8/thread, f32x2.
// ---------------------------------------------------------------------------
#define JCc 32
#define ATS 68
__global__ void k_gat_agg(const int* __restrict__ adj, int layer, int last)
{
    const int b  = blockIdx.z;
    const int i0 = blockIdx.x * 64;
    const int c0 = blockIdx.y * 64;
    const int t  = threadIdx.x;            // 0..127
    const int tx = t & 7, ty = t >> 3;     // tx: col group, ty: row group
    const int lane = t & 31, warp = t >> 5;

    const float* s1 = g_zbuf + layer*2*BN;
    const float* s2 = s1 + BN;

    __shared__ float s2_sh[Nv];
    __shared__ __align__(16) float att[Nv * ATS];     // [j][i_local]
    __shared__ __align__(16) float sh[2][JCc * 64];   // h chunks [j][c]

    const uint32_t sha = (uint32_t)__cvta_generic_to_shared(sh);
    const float* hb = g_h + (size_t)b*Nv*Hv;

#define ISSUE_H(jc, buf)                                                       \
    {                                                                          \
        _Pragma("unroll")                                                      \
        for (int m = 0; m < 4; ++m) {                                          \
            int idx = t + 128*m;                                               \
            int k = idx >> 4, f = idx & 15;                                    \
            uint32_t off = ((buf)*JCc*64 + k*64 + f*4)*4;                      \
            cp16(sha + off, &hb[(size_t)((jc)+k)*Hv + c0 + f*4]);              \
        }                                                                      \
        CP_COMMIT();                                                           \
    }

    ISSUE_H(0, 0);       // overlap with softmax

    s2_sh[t] = s2[b*Nv + t];
    __syncthreads();

    // softmax: 16 rows per warp (4 warps x 16 = 64 rows)
#pragma unroll 4
    for (int rr = 0; rr < 16; ++rr) {
        int il = warp*16 + rr;
        int i  = i0 + il;
        float s1i = s1[b*Nv + i];
        const int* adj_row = adj + (size_t)(b*Nv + i)*Nv;
        float e[4];
        float mx = NEG_INF;
#pragma unroll
        for (int q = 0; q < 4; ++q) {
            int jj = lane + q*32;
            float v = s1i + s2_sh[jj];
            v = (v > 0.f) ? v : ALPHA * v;
            v = (adj_row[jj] > 0) ? v : NEG_INF;
            e[q] = v;
            mx = fmaxf(mx, v);
        }
#pragma unroll
        for (int off = 16; off > 0; off >>= 1)
            mx = fmaxf(mx, __shfl_xor_sync(0xffffffffu, mx, off));
        float sum = 0.f;
#pragma unroll
        for (int q = 0; q < 4; ++q) { e[q] = __expf(e[q] - mx); sum += e[q]; }
#pragma unroll
        for (int off = 16; off > 0; off >>= 1)
            sum += __shfl_xor_sync(0xffffffffu, sum, off);
        float inv = 1.f / sum;
#pragma unroll
        for (int q = 0; q < 4; ++q)
            att[(lane + q*32)*ATS + il] = e[q] * inv;
    }

    u64 acc[4][4];
#pragma unroll
    for (int r = 0; r < 4; ++r)
#pragma unroll
        for (int p = 0; p < 4; ++p) acc[r][p] = pack2(0.f, 0.f);

    const int NJC = Nv / JCc;      // 4
#pragma unroll
    for (int c = 0; c < NJC; ++c) {
        const int cur = c & 1;
        if (c + 1 < NJC) {
            ISSUE_H((c+1)*JCc, (c+1)&1);
            CP_WAIT1();
        } else {
            CP_WAIT0();
        }
        __syncthreads();

#pragma unroll 8
        for (int k = 0; k < JCc; ++k) {
            int j = c*JCc + k;
            float4 ia = *reinterpret_cast<const float4*>(&att[j*ATS + ty*4]);
            const u64* hp = reinterpret_cast<const u64*>(&sh[cur][k*64 + tx*4]);
            const u64* hq = reinterpret_cast<const u64*>(&sh[cur][k*64 + 32 + tx*4]);
            u64 h0 = hp[0], h1 = hp[1], h2 = hq[0], h3 = hq[1];
            u64 i0p = pack2(ia.x, ia.x);
            u64 i1p = pack2(ia.y, ia.y);
            u64 i2p = pack2(ia.z, ia.z);
            u64 i3p = pack2(ia.w, ia.w);
            fma2(acc[0][0], i0p, h0); fma2(acc[0][1], i0p, h1);
            fma2(acc[0][2], i0p, h2); fma2(acc[0][3], i0p, h3);
            fma2(acc[1][0], i1p, h0); fma2(acc[1][1], i1p, h1);
            fma2(acc[1][2], i1p, h2); fma2(acc[1][3], i1p, h3);
            fma2(acc[2][0], i2p, h0); fma2(acc[2][1], i2p, h1);
            fma2(acc[2][2], i2p, h2); fma2(acc[2][3], i2p, h3);
            fma2(acc[3][0], i3p, h0); fma2(acc[3][1], i3p, h1);
            fma2(acc[3][2], i3p, h2); fma2(acc[3][3], i3p, h3);
        }
        __syncthreads();
    }
#undef ISSUE_H

    // thread holds rows i0+ty*4+{0..3}, cols c0 + {tx*4..+3, 32+tx*4..+3}
    if (last) {
        float* graph = g_zbuf + GRAPH_OFF;
        float colsum[8];
#pragma unroll
        for (int q = 0; q < 8; ++q) colsum[q] = 0.f;
#pragma unroll
        for (int r = 0; r < 4; ++r) {
            float2 v0 = unpack2(acc[r][0]);
            float2 v1 = unpack2(acc[r][1]);
            float2 v2 = unpack2(acc[r][2]);
            float2 v3 = unpack2(acc[r][3]);
            colsum[0] += fmaxf(v0.x, 0.f); colsum[1] += fmaxf(v0.y, 0.f);
            colsum[2] += fmaxf(v1.x, 0.f); colsum[3] += fmaxf(v1.y, 0.f);
            colsum[4] += fmaxf(v2.x, 0.f); colsum[5] += fmaxf(v2.y, 0.f);
            colsum[6] += fmaxf(v3.x, 0.f); colsum[7] += fmaxf(v3.y, 0.f);
        }
#pragma unroll
        for (int q = 0; q < 8; ++q) {
            int col = (q < 4) ? (tx*4 + q) : (32 + tx*4 + q - 4);
            atomicAdd(&graph[b*Hv + c0 + col], colsum[q]);
        }
    } else {
        // transpose relu through smem (reuse att as st[i][c], stride 68)
        __syncthreads();
        float* st = att;
#pragma unroll
        for (int r = 0; r < 4; ++r) {
            int il = ty*4 + r;
            float2 v0 = unpack2(acc[r][0]);
            float2 v1 = unpack2(acc[r][1]);
            float2 v2 = unpack2(acc[r][2]);
            float2 v3 = unpack2(acc[r][3]);
            st[il*68 + tx*4 + 0]      = fmaxf(v0.x, 0.f);
            st[il*68 + tx*4 + 1]      = fmaxf(v0.y, 0.f);
            st[il*68 + tx*4 + 2]      = fmaxf(v1.x, 0.f);
            st[il*68 + tx*4 + 3]      = fmaxf(v1.y, 0.f);
            st[il*68 + 32 + tx*4 + 0] = fmaxf(v2.x, 0.f);
            st[il*68 + 32 + tx*4 + 1] = fmaxf(v2.y, 0.f);
            st[il*68 + 32 + tx*4 + 2] = fmaxf(v3.x, 0.f);
            st[il*68 + 32 + tx*4 + 3] = fmaxf(v3.y, 0.f);
        }
        __syncthreads();
        // thread t: channel c = t&63, row-half = t>>6
        int ch   = t & 63;
        int half = t >> 6;
        float* dst = &g_xT[(size_t)(c0 + ch)*BN + b*Nv + i0 + half*32];
#pragma unroll
        for (int q = 0; q < 8; ++q) {
            int i = half*32 + 4*q;
            float4 o = make_float4(st[(i+0)*68 + ch], st[(i+1)*68 + ch],
                                   st[(i+2)*68 + ch], st[(i+3)*68 + ch]);
            *reinterpret_cast<float4*>(dst + 4*q) = o;
        }
    }
}

// ---------------------------------------------------------------------------
// K5: fused head. One block per batch element.
// ---------------------------------------------------------------------------
__global__ void k_head(const float* __restrict__ scaffold,
                       const float* __restrict__ W_sc,
                       const float* __restrict__ b_sc,
                       const float* __restrict__ gp_w1,
                       const float* __restrict__ gp_b1,
                       const float* __restrict__ gp_w2,
                       const float* __restrict__ gp_b2,
                       const float* __restrict__ out_w1,
                       const float* __restrict__ out_b1,
                       const float* __restrict__ out_w2,
                       const float* __restrict__ out_b2,
                       float* __restrict__ out)
{
    int b = blockIdx.x, t = threadIdx.x;
    const float* graph = g_zbuf + GRAPH_OFF;
    __shared__ float scaf[Sv];
    __shared__ float grow[Hv];
    __shared__ float sc[Hv];
    __shared__ float g1[128], sp1[128];
    __shared__ float c[128];
    __shared__ float hdn[128];

    if (t < Sv) scaf[t] = scaffold[b*Sv + t];
    grow[t] = graph[b*Hv + t] * (1.0f/Nv);
    __syncthreads();

    {
        float acc = b_sc[t];
#pragma unroll
        for (int k = 0; k < Sv; ++k)
            acc += scaf[k] * W_sc[k*Hv + t];
        sc[t] = acc;
    }
    __syncthreads();

    {
        int col = t & 127;
        const float* src = (t < 128) ? grow : sc;
        float acc = gp_b1[col];
#pragma unroll 4
        for (int k = 0; k < Hv; ++k)
            acc += src[k] * gp_w1[k*128 + col];
        acc = fmaxf(acc, 0.f);
        if (t < 128) g1[col] = acc; else sp1[col] = acc;
    }
    __syncthreads();

    if (t < 128) {
        int col = t & 63;
        const float* src = (t < 64) ? g1 : sp1;
        float acc = gp_b2[col];
#pragma unroll 4
        for (int k = 0; k < 128; ++k)
            acc += src[k] * gp_w2[k*64 + col];
        c[t] = fmaxf(acc, 0.f);
    }
    __syncthreads();

    if (t < 128) {
        float acc = out_b1[t];
#pragma unroll 4
        for (int k = 0; k < 128; ++k)
            acc += c[k] * out_w1[k*128 + t];
        hdn[t] = fmaxf(acc, 0.f);
    }
    __syncthreads();

    if (t < Tv) {
        float acc = out_b2[t];
#pragma unroll 4
        for (int k = 0; k < 128; ++k)
            acc += hdn[k] * out_w2[k*Tv + t];
        out[b*Tv + t] = acc;
    }
}

// ---------------------------------------------------------------------------
extern "C" void kernel_launch(void* const* d_in, const int* in_sizes, int n_in,
                              void* d_out, int out_size)
{
    const float* node_features     = (const float*)d_in[0];
    // d_in[1] = edge_features — unused by the reference
    const int*   adj_matrix        = (const int*)  d_in[2];
    const float* scaffold_features = (const float*)d_in[3];
    const float* W_node            = (const float*)d_in[4];
    const float* b_node            = (const float*)d_in[5];
    const float* gat_W             = (const float*)d_in[6];
    const float* gat_a             = (const float*)d_in[7];
    const float* W_sc              = (const float*)d_in[8];
    const float* b_sc              = (const float*)d_in[9];
    const float* gp_w1             = (const float*)d_in[10];
    const float* gp_b1             = (const float*)d_in[11];
    const float* gp_w2             = (const float*)d_in[12];
    const float* gp_b2             = (const float*)d_in[13];
    const float* out_w1            = (const float*)d_in[14];
    const float* out_b1            = (const float*)d_in[15];
    const float* out_w2            = (const float*)d_in[16];
    const float* out_b2            = (const float*)d_in[17];
    float* out = (float*)d_out;

    void* zp = nullptr;
    cudaGetSymbolAddress(&zp, g_zbuf);
    cudaMemsetAsync(zp, 0, (Lv*2*BN + Bv*Hv)*sizeof(float));

    k_node_proj<<<BN/NP_ROWS, 256>>>(node_features, W_node, b_node);

    for (int l = 0; l < Lv; ++l) {
        dim3 pg(BN/64, Hv/64);                 // 64 x 4 = 256 blocks, 128 thr
        k_gat_proj<<<pg, 128>>>(gat_W + (size_t)l*Hv*Hv,
                                gat_a + (size_t)l*2*Hv, l);
        dim3 ag(Nv/64, Hv/64, Bv);             // 2 x 4 x 32 = 256 blocks, 128 thr
        k_gat_agg<<<ag, 128>>>(adj_matrix, l, l == Lv-1);
    }

    k_head<<<Bv, 256>>>(scaffold_features, W_sc, b_sc,
                        gp_w1, gp_b1, gp_w2, gp_b2,
                        out_w1, out_b1, out_w2, out_b2, out);
}